// round 1
// baseline (speedup 1.0000x reference)
#include <cuda_runtime.h>
#include <cstdint>

// Problem constants
#define BB 4
#define SS 2048
#define DD 1024
#define NHH 16
#define ADIM 64
#define MTOT (BB*SS)          // 8192

// Scratch (allocation-free rule: __device__ globals)
__device__ float g_qkv[(size_t)MTOT * 3 * DD];   // [8192][3072]  96 MB
__device__ float g_o[(size_t)MTOT * DD];         // [8192][1024]  32 MB

// ---------------------------------------------------------------------------
// tf32 helpers
// ---------------------------------------------------------------------------
__device__ __forceinline__ float tf32r(float x) {
    uint32_t u;
    asm("cvt.rna.tf32.f32 %0, %1;" : "=r"(u) : "f"(x));
    return __uint_as_float(u);
}

__device__ __forceinline__ void mma_tf32(float c[4], const uint32_t a[4], const uint32_t b[2]) {
    asm volatile(
        "mma.sync.aligned.m16n8k8.row.col.f32.tf32.tf32.f32 "
        "{%0,%1,%2,%3}, {%4,%5,%6,%7}, {%8,%9}, {%0,%1,%2,%3};\n"
        : "+f"(c[0]), "+f"(c[1]), "+f"(c[2]), "+f"(c[3])
        : "r"(a[0]), "r"(a[1]), "r"(a[2]), "r"(a[3]), "r"(b[0]), "r"(b[1]));
}

// ---------------------------------------------------------------------------
// Generic GEMM: C[M,N] = A[M,K] * B[N,K]^T   (fp32 in/out, tf32 mma)
// Tiles: 128x128x32, 256 threads (8 warps, warp tile 64x32).
// Requires M%128==0, N%128==0, K%32==0 (true for all call sites).
// ---------------------------------------------------------------------------
__global__ void __launch_bounds__(256) gemm_tf32_kernel(
    const float* __restrict__ A, const float* __restrict__ Bm,
    float* __restrict__ C, int M, int N, int K)
{
    __shared__ float As[128][36];
    __shared__ float Bs[128][36];

    const int tid  = threadIdx.x;
    const int warp = tid >> 5, lane = tid & 31;
    const int g = lane >> 2, t = lane & 3;
    const int wm = warp & 1;        // 0..1  (64 rows each)
    const int wn = warp >> 1;       // 0..3  (32 cols each)
    const int m0 = blockIdx.y * 128, n0 = blockIdx.x * 128;

    float acc[4][4][4];
    #pragma unroll
    for (int i = 0; i < 4; i++)
        #pragma unroll
        for (int j = 0; j < 4; j++)
            #pragma unroll
            for (int k = 0; k < 4; k++) acc[i][j][k] = 0.f;

    const int lrow = tid >> 3;   // 0..31
    const int lc4  = tid & 7;    // 0..7 (float4 col)

    for (int kt = 0; kt < K; kt += 32) {
        #pragma unroll
        for (int i = 0; i < 4; i++) {
            int row = lrow + i * 32;
            float4 va = *(const float4*)&A[(size_t)(m0 + row) * K + kt + lc4 * 4];
            float4 ca = make_float4(tf32r(va.x), tf32r(va.y), tf32r(va.z), tf32r(va.w));
            *(float4*)&As[row][lc4 * 4] = ca;
            float4 vb = *(const float4*)&Bm[(size_t)(n0 + row) * K + kt + lc4 * 4];
            float4 cb = make_float4(tf32r(vb.x), tf32r(vb.y), tf32r(vb.z), tf32r(vb.w));
            *(float4*)&Bs[row][lc4 * 4] = cb;
        }
        __syncthreads();

        #pragma unroll
        for (int ks = 0; ks < 4; ks++) {
            uint32_t a[4][4];
            #pragma unroll
            for (int mt = 0; mt < 4; mt++) {
                int r0 = wm * 64 + mt * 16 + g;
                a[mt][0] = __float_as_uint(As[r0    ][ks * 8 + t]);
                a[mt][1] = __float_as_uint(As[r0 + 8][ks * 8 + t]);
                a[mt][2] = __float_as_uint(As[r0    ][ks * 8 + t + 4]);
                a[mt][3] = __float_as_uint(As[r0 + 8][ks * 8 + t + 4]);
            }
            #pragma unroll
            for (int nt = 0; nt < 4; nt++) {
                int rb = wn * 32 + nt * 8 + g;
                uint32_t b[2];
                b[0] = __float_as_uint(Bs[rb][ks * 8 + t]);
                b[1] = __float_as_uint(Bs[rb][ks * 8 + t + 4]);
                #pragma unroll
                for (int mt = 0; mt < 4; mt++) mma_tf32(acc[mt][nt], a[mt], b);
            }
        }
        __syncthreads();
    }

    #pragma unroll
    for (int mt = 0; mt < 4; mt++) {
        int r0 = m0 + wm * 64 + mt * 16 + g;
        #pragma unroll
        for (int nt = 0; nt < 4; nt++) {
            int c0 = n0 + wn * 32 + nt * 8 + 2 * t;
            *(float2*)&C[(size_t)r0 * N + c0]       = make_float2(acc[mt][nt][0], acc[mt][nt][1]);
            *(float2*)&C[(size_t)(r0 + 8) * N + c0] = make_float2(acc[mt][nt][2], acc[mt][nt][3]);
        }
    }
}

// ---------------------------------------------------------------------------
// Fused squared-ReLU attention.
// Grid: (S/128, NH, B). Block: 256 threads (8 warps x 16 q-rows).
// For each 128-q tile: loop over 16 key tiles of 128:
//   S = Q K^T / 8 + bias ; t = relu(S)^2 ; rowsum += t ; O += t V
// Final: O /= (rowsum + 1e-32)
// ---------------------------------------------------------------------------
#define QS_STRIDE 68
#define SS_STRIDE 132
#define ATTN_SMEM_FLOATS (128*QS_STRIDE*2 + 64*SS_STRIDE + 128*SS_STRIDE)
#define ATTN_SMEM_BYTES  (ATTN_SMEM_FLOATS * 4)   // 171008 bytes

__global__ void __launch_bounds__(256) attn_kernel(
    const float* __restrict__ qkv, const float* __restrict__ sn_bias,
    float* __restrict__ o_out)
{
    extern __shared__ float sm[];
    float* Qs = sm;                               // [128][68]
    float* Ks = Qs + 128 * QS_STRIDE;             // [128][68]
    float* Vt = Ks + 128 * QS_STRIDE;             // [64][132]  (V transposed)
    float* Sb = Vt + 64 * SS_STRIDE;              // [128][132] (t values, tf32)

    const int tid  = threadIdx.x;
    const int warp = tid >> 5, lane = tid & 31;
    const int g = lane >> 2, t = lane & 3;
    const int qt = blockIdx.x, h = blockIdx.y, b = blockIdx.z;
    const float bias = sn_bias[0];

    // ---- load Q tile (once) : rows qt*128.., cols h*64.. of qkv[...,0,...]
    #pragma unroll
    for (int i = 0; i < 8; i++) {
        int idx = tid + i * 256;            // 0..2047
        int row = idx >> 4, c4 = idx & 15;  // 16 float4 per 64-col row
        size_t gp = ((size_t)(b * SS + qt * 128 + row)) * (3 * DD) + h * ADIM + c4 * 4;
        float4 v = *(const float4*)&qkv[gp];
        *(float4*)&Qs[row * QS_STRIDE + c4 * 4] =
            make_float4(tf32r(v.x), tf32r(v.y), tf32r(v.z), tf32r(v.w));
    }
    __syncthreads();

    const int row0 = warp * 16 + g;
    const int row1 = row0 + 8;

    float Oacc[8][4];
    #pragma unroll
    for (int i = 0; i < 8; i++)
        #pragma unroll
        for (int j = 0; j < 4; j++) Oacc[i][j] = 0.f;
    float rsum0 = 0.f, rsum1 = 0.f;

    for (int kt = 0; kt < 16; kt++) {
        // ---- load K tile + V tile (transposed into Vt)
        #pragma unroll
        for (int i = 0; i < 8; i++) {
            int idx = tid + i * 256;
            int row = idx >> 4, c4 = idx & 15;
            size_t gp = ((size_t)(b * SS + kt * 128 + row)) * (3 * DD) + h * ADIM + c4 * 4;
            float4 vk = *(const float4*)&qkv[gp + DD];
            *(float4*)&Ks[row * QS_STRIDE + c4 * 4] =
                make_float4(tf32r(vk.x), tf32r(vk.y), tf32r(vk.z), tf32r(vk.w));
            float4 vv = *(const float4*)&qkv[gp + 2 * DD];
            Vt[(c4 * 4 + 0) * SS_STRIDE + row] = tf32r(vv.x);
            Vt[(c4 * 4 + 1) * SS_STRIDE + row] = tf32r(vv.y);
            Vt[(c4 * 4 + 2) * SS_STRIDE + row] = tf32r(vv.z);
            Vt[(c4 * 4 + 3) * SS_STRIDE + row] = tf32r(vv.w);
        }
        __syncthreads();

        // ---- S = Q K^T  (per warp: 16 q-rows x 128 keys)
        float Sacc[16][4];
        #pragma unroll
        for (int i = 0; i < 16; i++)
            #pragma unroll
            for (int j = 0; j < 4; j++) Sacc[i][j] = 0.f;

        #pragma unroll
        for (int ks = 0; ks < 8; ks++) {
            uint32_t a[4];
            a[0] = __float_as_uint(Qs[row0 * QS_STRIDE + ks * 8 + t]);
            a[1] = __float_as_uint(Qs[row1 * QS_STRIDE + ks * 8 + t]);
            a[2] = __float_as_uint(Qs[row0 * QS_STRIDE + ks * 8 + t + 4]);
            a[3] = __float_as_uint(Qs[row1 * QS_STRIDE + ks * 8 + t + 4]);
            #pragma unroll
            for (int nt = 0; nt < 16; nt++) {
                uint32_t bb[2];
                bb[0] = __float_as_uint(Ks[(nt * 8 + g) * QS_STRIDE + ks * 8 + t]);
                bb[1] = __float_as_uint(Ks[(nt * 8 + g) * QS_STRIDE + ks * 8 + t + 4]);
                mma_tf32(Sacc[nt], a, bb);
            }
        }

        // ---- t = relu(S/8 + bias)^2 ; rowsum ; stash tf32(t) in smem
        #pragma unroll
        for (int nt = 0; nt < 16; nt++) {
            float v0 = fmaxf(Sacc[nt][0] * 0.125f + bias, 0.f); v0 *= v0;
            float v1 = fmaxf(Sacc[nt][1] * 0.125f + bias, 0.f); v1 *= v1;
            float v2 = fmaxf(Sacc[nt][2] * 0.125f + bias, 0.f); v2 *= v2;
            float v3 = fmaxf(Sacc[nt][3] * 0.125f + bias, 0.f); v3 *= v3;
            rsum0 += v0 + v1;
            rsum1 += v2 + v3;
            int c = nt * 8 + 2 * t;
            Sb[row0 * SS_STRIDE + c]     = tf32r(v0);
            Sb[row0 * SS_STRIDE + c + 1] = tf32r(v1);
            Sb[row1 * SS_STRIDE + c]     = tf32r(v2);
            Sb[row1 * SS_STRIDE + c + 1] = tf32r(v3);
        }
        __syncwarp();   // Sb rows are warp-private: warp-level fence suffices

        // ---- O += t * V  (A = t [16 x 128], B = Vt [64 x 128] as [n][k])
        #pragma unroll
        for (int ks = 0; ks < 16; ks++) {
            uint32_t a[4];
            a[0] = __float_as_uint(Sb[row0 * SS_STRIDE + ks * 8 + t]);
            a[1] = __float_as_uint(Sb[row1 * SS_STRIDE + ks * 8 + t]);
            a[2] = __float_as_uint(Sb[row0 * SS_STRIDE + ks * 8 + t + 4]);
            a[3] = __float_as_uint(Sb[row1 * SS_STRIDE + ks * 8 + t + 4]);
            #pragma unroll
            for (int dt = 0; dt < 8; dt++) {
                uint32_t bb[2];
                bb[0] = __float_as_uint(Vt[(dt * 8 + g) * SS_STRIDE + ks * 8 + t]);
                bb[1] = __float_as_uint(Vt[(dt * 8 + g) * SS_STRIDE + ks * 8 + t + 4]);
                mma_tf32(Oacc[dt], a, bb);
            }
        }
        __syncthreads();   // Ks/Vt about to be overwritten
    }

    // ---- normalize and write O
    rsum0 += __shfl_xor_sync(0xffffffffu, rsum0, 1);
    rsum0 += __shfl_xor_sync(0xffffffffu, rsum0, 2);
    rsum1 += __shfl_xor_sync(0xffffffffu, rsum1, 1);
    rsum1 += __shfl_xor_sync(0xffffffffu, rsum1, 2);
    float inv0 = 1.f / (rsum0 + 1e-32f);
    float inv1 = 1.f / (rsum1 + 1e-32f);

    size_t ob0 = ((size_t)(b * SS + qt * 128 + row0)) * DD + h * ADIM;
    size_t ob1 = ((size_t)(b * SS + qt * 128 + row1)) * DD + h * ADIM;
    #pragma unroll
    for (int dt = 0; dt < 8; dt++) {
        int c = dt * 8 + 2 * t;
        *(float2*)&o_out[ob0 + c] = make_float2(Oacc[dt][0] * inv0, Oacc[dt][1] * inv0);
        *(float2*)&o_out[ob1 + c] = make_float2(Oacc[dt][2] * inv1, Oacc[dt][3] * inv1);
    }
}

// ---------------------------------------------------------------------------
// Launch
// ---------------------------------------------------------------------------
extern "C" void kernel_launch(void* const* d_in, const int* in_sizes, int n_in,
                              void* d_out, int out_size)
{
    const float* iQ      = (const float*)d_in[0];
    const float* w_qkv   = (const float*)d_in[1];
    const float* w_out   = (const float*)d_in[2];
    const float* sn_bias = (const float*)d_in[3];
    float* out = (float*)d_out;

    (void)in_sizes; (void)n_in; (void)out_size;

    cudaFuncSetAttribute(attn_kernel,
                         cudaFuncAttributeMaxDynamicSharedMemorySize, ATTN_SMEM_BYTES);

    float *qkvp = nullptr, *op = nullptr;
    cudaGetSymbolAddress((void**)&qkvp, g_qkv);
    cudaGetSymbolAddress((void**)&op, g_o);

    // 1) qkv = iQ @ w_qkv^T : [8192,1024] x [3072,1024]^T -> [8192,3072]
    gemm_tf32_kernel<<<dim3(3 * DD / 128, MTOT / 128), 256>>>(
        iQ, w_qkv, qkvp, MTOT, 3 * DD, DD);

    // 2) fused squared-ReLU attention -> g_o [8192,1024]
    attn_kernel<<<dim3(SS / 128, NHH, BB), 256, ATTN_SMEM_BYTES>>>(
        qkvp, sn_bias, op);

    // 3) out = o @ w_out^T : [8192,1024] x [1024,1024]^T -> [8192,1024]
    gemm_tf32_kernel<<<dim3(DD / 128, MTOT / 128), 256>>>(
        op, w_out, out, MTOT, DD, DD);
}

// round 3
// speedup vs baseline: 1.1955x; 1.1955x over previous
#include <cuda_runtime.h>
#include <cstdint>

// Problem constants
#define BB 4
#define SS 2048
#define DD 1024
#define NHH 16
#define ADIM 64
#define MTOT (BB*SS)          // 8192

// ---------------------------------------------------------------------------
// Scratch (allocation-free rule: __device__ globals)
// ---------------------------------------------------------------------------
__device__ __align__(1024) float g_qkv[(size_t)MTOT * 3 * DD];   // 96 MB
__device__ __align__(1024) float g_o[(size_t)MTOT * DD];         // 32 MB
__device__ __align__(1024) float g_a[(size_t)MTOT * DD];         // rounded iQ
__device__ __align__(1024) float g_b[(size_t)3 * DD * DD];       // rounded w_qkv
__device__ __align__(1024) float g_w[(size_t)DD * DD];           // rounded w_out

// ---------------------------------------------------------------------------
// helpers
// ---------------------------------------------------------------------------
__device__ __forceinline__ float tf32r(float x) {
    uint32_t u;
    asm("cvt.rna.tf32.f32 %0, %1;" : "=r"(u) : "f"(x));
    return __uint_as_float(u);
}

__device__ __forceinline__ uint32_t smem_u32(const void* p) {
    uint32_t a;
    asm("{ .reg .u64 t; cvta.to.shared.u64 t, %1; cvt.u32.u64 %0, t; }" : "=r"(a) : "l"(p));
    return a;
}

__device__ __forceinline__ void mma_tf32(float c[4], const uint32_t a[4], const uint32_t b0, const uint32_t b1) {
    asm volatile(
        "mma.sync.aligned.m16n8k8.row.col.f32.tf32.tf32.f32 "
        "{%0,%1,%2,%3}, {%4,%5,%6,%7}, {%8,%9}, {%0,%1,%2,%3};\n"
        : "+f"(c[0]), "+f"(c[1]), "+f"(c[2]), "+f"(c[3])
        : "r"(a[0]), "r"(a[1]), "r"(a[2]), "r"(a[3]), "r"(b0), "r"(b1));
}

#define LDM_X4(r0,r1,r2,r3, addr) \
    asm volatile("ldmatrix.sync.aligned.m8n8.x4.shared.b16 {%0,%1,%2,%3}, [%4];" \
        : "=r"(r0), "=r"(r1), "=r"(r2), "=r"(r3) : "r"(addr))

__device__ __forceinline__ void cp16(uint32_t dst, const void* src) {
    asm volatile("cp.async.cg.shared.global [%0], [%1], 16;" :: "r"(dst), "l"(src));
}
#define CP_COMMIT() asm volatile("cp.async.commit_group;" ::: "memory")
#define CP_WAIT2()  asm volatile("cp.async.wait_group 2;" ::: "memory")

// ---------------------------------------------------------------------------
// tf32 pre-round
// ---------------------------------------------------------------------------
__global__ void __launch_bounds__(256) tf32_round_kernel(
    const float4* __restrict__ in, float4* __restrict__ out)
{
    int i = blockIdx.x * 256 + threadIdx.x;
    float4 v = in[i];
    out[i] = make_float4(tf32r(v.x), tf32r(v.y), tf32r(v.z), tf32r(v.w));
}

// ---------------------------------------------------------------------------
// GEMM: C[M,N] = A[M,K] * B[N,K]^T. Inputs pre-rounded to tf32 values.
// 128x128x32 tiles, 256 thr (8 warps, 64x32 each), 3-stage cp.async, ldmatrix.
// ---------------------------------------------------------------------------
#define GPAD 36
#define GSTG_FLOATS (2 * 128 * GPAD)            // As+Bs per stage = 9216 floats
#define GSM_BYTES   (3 * GSTG_FLOATS * 4)       // 110592

__global__ void __launch_bounds__(256, 2) gemm_tc_kernel(
    const float* __restrict__ A, const float* __restrict__ Bm,
    float* __restrict__ C, int N, int K)
{
    extern __shared__ float sm[];
    const uint32_t sm_base = smem_u32(sm);

    const int tid  = threadIdx.x;
    const int warp = tid >> 5, lane = tid & 31;
    const int t = lane & 3;
    const int wm = warp & 1;        // row half (64)
    const int wn = warp >> 1;       // col quarter (32)
    const int m0 = blockIdx.y * 128, n0 = blockIdx.x * 128;
    const int NKT = K >> 5;

    const int lrow = tid >> 3;      // 0..31
    const int lc4  = tid & 7;       // 0..7

    // ldmatrix per-lane address components (byte offsets into a stage)
    const uint32_t aOff = (uint32_t)((wm * 64 + (lane & 15)) * GPAD + ((lane & 16) >> 2)) * 4;
    const uint32_t bOff = (uint32_t)(((lane & 7) + ((lane & 16) >> 1)) * GPAD + ((lane & 8) >> 1)) * 4
                          + (uint32_t)(wn * 32 * GPAD) * 4;

    float acc[4][4][4];
    #pragma unroll
    for (int i = 0; i < 4; i++)
        #pragma unroll
        for (int j = 0; j < 4; j++)
            #pragma unroll
            for (int k = 0; k < 4; k++) acc[i][j][k] = 0.f;

    auto issue = [&](int kt) {
        uint32_t sA = sm_base + (uint32_t)(kt % 3) * (GSTG_FLOATS * 4);
        uint32_t sB = sA + 128 * GPAD * 4;
        #pragma unroll
        for (int i = 0; i < 4; i++) {
            int row = lrow + i * 32;
            uint32_t so = (uint32_t)(row * GPAD + lc4 * 4) * 4;
            cp16(sA + so, &A[(size_t)(m0 + row) * K + kt * 32 + lc4 * 4]);
            cp16(sB + so, &Bm[(size_t)(n0 + row) * K + kt * 32 + lc4 * 4]);
        }
    };

    issue(0); CP_COMMIT();
    issue(1); CP_COMMIT();
    issue(2); CP_COMMIT();

    for (int kt = 0; kt < NKT; kt++) {
        CP_WAIT2();
        __syncthreads();
        uint32_t sA = sm_base + (uint32_t)(kt % 3) * (GSTG_FLOATS * 4);
        uint32_t sB = sA + 128 * GPAD * 4;

        #pragma unroll
        for (int ks = 0; ks < 4; ks++) {
            uint32_t a[4][4];
            #pragma unroll
            for (int mt = 0; mt < 4; mt++)
                LDM_X4(a[mt][0], a[mt][1], a[mt][2], a[mt][3],
                       sA + aOff + (uint32_t)(mt * 16 * GPAD + ks * 8) * 4);
            #pragma unroll
            for (int p = 0; p < 2; p++) {
                uint32_t b0, b1, b2, b3;
                LDM_X4(b0, b1, b2, b3, sB + bOff + (uint32_t)(p * 16 * GPAD + ks * 8) * 4);
                #pragma unroll
                for (int mt = 0; mt < 4; mt++) {
                    mma_tf32(acc[mt][2 * p],     a[mt], b0, b1);
                    mma_tf32(acc[mt][2 * p + 1], a[mt], b2, b3);
                }
            }
        }
        __syncthreads();
        if (kt + 3 < NKT) issue(kt + 3);
        CP_COMMIT();
    }

    const int g = lane >> 2;
    #pragma unroll
    for (int mt = 0; mt < 4; mt++) {
        int r0 = m0 + wm * 64 + mt * 16 + g;
        #pragma unroll
        for (int nt = 0; nt < 4; nt++) {
            int c0 = n0 + wn * 32 + nt * 8 + 2 * t;
            *(float2*)&C[(size_t)r0 * N + c0]       = make_float2(acc[mt][nt][0], acc[mt][nt][1]);
            *(float2*)&C[(size_t)(r0 + 8) * N + c0] = make_float2(acc[mt][nt][2], acc[mt][nt][3]);
        }
    }
}

// ---------------------------------------------------------------------------
// Fused squared-ReLU attention, v2: ldmatrix fragments + shuffle-based
// accum->A-frag conversion (no Sb). smem 103KB -> 2 CTAs/SM.
// Grid: (S/128, NH, B). Block 256 (8 warps x 16 q-rows).
// ---------------------------------------------------------------------------
#define QK_STRIDE 68
#define VT_STRIDE 132
#define ATTN_SMEM_FLOATS (128*QK_STRIDE*2 + 64*VT_STRIDE)
#define ATTN_SMEM_BYTES  (ATTN_SMEM_FLOATS * 4)   // 103424

__global__ void __launch_bounds__(256, 2) attn_kernel(
    const float* __restrict__ qkv, const float* __restrict__ sn_bias,
    float* __restrict__ o_out)
{
    extern __shared__ float sm[];
    float* Qs = sm;                               // [128][68]
    float* Ks = Qs + 128 * QK_STRIDE;             // [128][68]
    float* Vt = Ks + 128 * QK_STRIDE;             // [64][132]

    const uint32_t Qs_u = smem_u32(Qs);
    const uint32_t Ks_u = smem_u32(Ks);
    const uint32_t Vt_u = smem_u32(Vt);

    const int tid  = threadIdx.x;
    const int warp = tid >> 5, lane = tid & 31;
    const int g = lane >> 2, t = lane & 3;
    const int qt = blockIdx.x, h = blockIdx.y, b = blockIdx.z;
    const float bias = sn_bias[0];

    // ldmatrix lane-address components (byte offsets)
    const uint32_t qOff = (uint32_t)((warp * 16 + (lane & 15)) * QK_STRIDE + ((lane & 16) >> 2)) * 4;
    const uint32_t kOff = (uint32_t)(((lane & 7) + ((lane & 16) >> 1)) * QK_STRIDE + ((lane & 8) >> 1)) * 4;
    const uint32_t vOff = (uint32_t)(((lane & 7) + ((lane & 16) >> 1)) * VT_STRIDE + ((lane & 8) >> 1)) * 4;

    const int srcA = (lane & ~3) | (t >> 1);
    const int srcB = (lane & ~3) | ((t >> 1) + 2);
    const bool odd = (t & 1);

    // ---- load Q tile
    #pragma unroll
    for (int i = 0; i < 8; i++) {
        int idx = tid + i * 256;
        int row = idx >> 4, c4 = idx & 15;
        size_t gp = ((size_t)(b * SS + qt * 128 + row)) * (3 * DD) + h * ADIM + c4 * 4;
        float4 v = *(const float4*)&qkv[gp];
        *(float4*)&Qs[row * QK_STRIDE + c4 * 4] =
            make_float4(tf32r(v.x), tf32r(v.y), tf32r(v.z), tf32r(v.w));
    }
    __syncthreads();

    float Oacc[8][4];
    #pragma unroll
    for (int i = 0; i < 8; i++)
        #pragma unroll
        for (int j = 0; j < 4; j++) Oacc[i][j] = 0.f;
    float rsum0 = 0.f, rsum1 = 0.f;

    for (int kt = 0; kt < 16; kt++) {
        // ---- K -> Ks (row-major), V -> Vt (transposed)
        #pragma unroll
        for (int i = 0; i < 8; i++) {
            int idx = tid + i * 256;
            int row = idx >> 4, c4 = idx & 15;
            size_t gp = ((size_t)(b * SS + kt * 128 + row)) * (3 * DD) + h * ADIM + c4 * 4;
            float4 vk = *(const float4*)&qkv[gp + DD];
            *(float4*)&Ks[row * QK_STRIDE + c4 * 4] =
                make_float4(tf32r(vk.x), tf32r(vk.y), tf32r(vk.z), tf32r(vk.w));
            float4 vv = *(const float4*)&qkv[gp + 2 * DD];
            Vt[(c4 * 4 + 0) * VT_STRIDE + row] = tf32r(vv.x);
            Vt[(c4 * 4 + 1) * VT_STRIDE + row] = tf32r(vv.y);
            Vt[(c4 * 4 + 2) * VT_STRIDE + row] = tf32r(vv.z);
            Vt[(c4 * 4 + 3) * VT_STRIDE + row] = tf32r(vv.w);
        }
        __syncthreads();

        // ---- S = Q K^T  (warp: 16 q-rows x 128 keys)
        float Sacc[16][4];
        #pragma unroll
        for (int i = 0; i < 16; i++)
            #pragma unroll
            for (int j = 0; j < 4; j++) Sacc[i][j] = 0.f;

        #pragma unroll
        for (int ks = 0; ks < 8; ks++) {
            uint32_t a[4];
            LDM_X4(a[0], a[1], a[2], a[3], Qs_u + qOff + (uint32_t)(ks * 8) * 4);
            #pragma unroll
            for (int p = 0; p < 8; p++) {
                uint32_t b0, b1, b2, b3;
                LDM_X4(b0, b1, b2, b3,
                       Ks_u + kOff + (uint32_t)(p * 16 * QK_STRIDE + ks * 8) * 4);
                mma_tf32(Sacc[2 * p],     a, b0, b1);
                mma_tf32(Sacc[2 * p + 1], a, b2, b3);
            }
        }

        // ---- per 8-key block: relu^2, rowsum, shuffle to A-frag, O-mma
        #pragma unroll
        for (int nt = 0; nt < 16; nt++) {
            float v0 = fmaxf(Sacc[nt][0] * 0.125f + bias, 0.f); v0 *= v0;
            float v1 = fmaxf(Sacc[nt][1] * 0.125f + bias, 0.f); v1 *= v1;
            float v2 = fmaxf(Sacc[nt][2] * 0.125f + bias, 0.f); v2 *= v2;
            float v3 = fmaxf(Sacc[nt][3] * 0.125f + bias, 0.f); v3 *= v3;
            rsum0 += v0 + v1;
            rsum1 += v2 + v3;
            float r0 = tf32r(v0), r1 = tf32r(v1), r2 = tf32r(v2), r3 = tf32r(v3);

            // redistribute cols (g,2t),(g,2t+1) -> (g,t),(g,t+4)
            float x0 = __shfl_sync(0xffffffffu, r0, srcA);
            float x1 = __shfl_sync(0xffffffffu, r1, srcA);
            float x2 = __shfl_sync(0xffffffffu, r2, srcA);
            float x3 = __shfl_sync(0xffffffffu, r3, srcA);
            float y0 = __shfl_sync(0xffffffffu, r0, srcB);
            float y1 = __shfl_sync(0xffffffffu, r1, srcB);
            float y2 = __shfl_sync(0xffffffffu, r2, srcB);
            float y3 = __shfl_sync(0xffffffffu, r3, srcB);

            uint32_t aF[4];
            aF[0] = __float_as_uint(odd ? x1 : x0);   // (g,   t)
            aF[1] = __float_as_uint(odd ? x3 : x2);   // (g+8, t)
            aF[2] = __float_as_uint(odd ? y1 : y0);   // (g,   t+4)
            aF[3] = __float_as_uint(odd ? y3 : y2);   // (g+8, t+4)

            #pragma unroll
            for (int p = 0; p < 4; p++) {
                uint32_t b0, b1, b2, b3;
                LDM_X4(b0, b1, b2, b3,
                       Vt_u + vOff + (uint32_t)(p * 16 * VT_STRIDE + nt * 8) * 4);
                mma_tf32(Oacc[2 * p],     aF, b0, b1);
                mma_tf32(Oacc[2 * p + 1], aF, b2, b3);
            }
        }
        __syncthreads();
    }

    // ---- normalize and write (tf32-rounded: feeds out-proj GEMM)
    rsum0 += __shfl_xor_sync(0xffffffffu, rsum0, 1);
    rsum0 += __shfl_xor_sync(0xffffffffu, rsum0, 2);
    rsum1 += __shfl_xor_sync(0xffffffffu, rsum1, 1);
    rsum1 += __shfl_xor_sync(0xffffffffu, rsum1, 2);
    float inv0 = 1.f / (rsum0 + 1e-32f);
    float inv1 = 1.f / (rsum1 + 1e-32f);

    const int row0 = warp * 16 + g;
    size_t ob0 = ((size_t)(b * SS + qt * 128 + row0)) * DD + h * ADIM;
    size_t ob1 = ob0 + 8 * DD;
    #pragma unroll
    for (int dt = 0; dt < 8; dt++) {
        int c = dt * 8 + 2 * t;
        *(float2*)&o_out[ob0 + c] = make_float2(tf32r(Oacc[dt][0] * inv0), tf32r(Oacc[dt][1] * inv0));
        *(float2*)&o_out[ob1 + c] = make_float2(tf32r(Oacc[dt][2] * inv1), tf32r(Oacc[dt][3] * inv1));
    }
}

// ---------------------------------------------------------------------------
// Launch
// ---------------------------------------------------------------------------
extern "C" void kernel_launch(void* const* d_in, const int* in_sizes, int n_in,
                              void* d_out, int out_size)
{
    const float* iQ      = (const float*)d_in[0];
    const float* w_qkv   = (const float*)d_in[1];
    const float* w_out   = (const float*)d_in[2];
    const float* sn_bias = (const float*)d_in[3];
    float* out = (float*)d_out;
    (void)in_sizes; (void)n_in; (void)out_size;

    cudaFuncSetAttribute(attn_kernel,
                         cudaFuncAttributeMaxDynamicSharedMemorySize, ATTN_SMEM_BYTES);
    cudaFuncSetAttribute(gemm_tc_kernel,
                         cudaFuncAttributeMaxDynamicSharedMemorySize, GSM_BYTES);

    float *qkvp = nullptr, *op = nullptr, *ap = nullptr, *bp = nullptr, *wp = nullptr;
    cudaGetSymbolAddress((void**)&qkvp, g_qkv);
    cudaGetSymbolAddress((void**)&op, g_o);
    cudaGetSymbolAddress((void**)&ap, g_a);
    cudaGetSymbolAddress((void**)&bp, g_b);
    cudaGetSymbolAddress((void**)&wp, g_w);

    // 0) pre-round inputs to tf32 values (GEMM loads them raw via cp.async)
    tf32_round_kernel<<<(MTOT * DD) / 1024, 256>>>((const float4*)iQ, (float4*)ap);
    tf32_round_kernel<<<(3 * DD * DD) / 1024, 256>>>((const float4*)w_qkv, (float4*)bp);
    tf32_round_kernel<<<(DD * DD) / 1024, 256>>>((const float4*)w_out, (float4*)wp);

    // 1) qkv = iQ @ w_qkv^T : [8192,1024] x [3072,1024]^T
    gemm_tc_kernel<<<dim3(3 * DD / 128, MTOT / 128), 256, GSM_BYTES>>>(
        ap, bp, qkvp, 3 * DD, DD);

    // 2) fused squared-ReLU attention -> g_o (tf32-rounded)
    attn_kernel<<<dim3(SS / 128, NHH, BB), 256, ATTN_SMEM_BYTES>>>(
        qkvp, sn_bias, op);

    // 3) out = o @ w_out^T : [8192,1024] x [1024,1024]^T
    gemm_tc_kernel<<<dim3(DD / 128, MTOT / 128), 256, GSM_BYTES>>>(
        op, wp, out, DD, DD);
}

// round 5
// speedup vs baseline: 2.4923x; 2.0847x over previous
#include <cuda_runtime.h>
#include <cuda_fp16.h>
#include <cstdint>

// Problem constants
#define BB 4
#define SS 2048
#define DD 1024
#define NHH 16
#define ADIM 64
#define MTOT (BB*SS)          // 8192

// ---------------------------------------------------------------------------
// Scratch (allocation-free rule: __device__ globals) — all fp16 now
// ---------------------------------------------------------------------------
__device__ __align__(1024) __half g_qkv[(size_t)MTOT * 3 * DD];   // 48 MB
__device__ __align__(1024) __half g_o[(size_t)MTOT * DD];         // 16 MB
__device__ __align__(1024) __half g_a[(size_t)MTOT * DD];         // rounded iQ
__device__ __align__(1024) __half g_b[(size_t)3 * DD * DD];       // rounded w_qkv
__device__ __align__(1024) __half g_w[(size_t)DD * DD];           // rounded w_out

// ---------------------------------------------------------------------------
// helpers
// ---------------------------------------------------------------------------
__device__ __forceinline__ uint32_t smem_u32(const void* p) {
    uint32_t a;
    asm("{ .reg .u64 t; cvta.to.shared.u64 t, %1; cvt.u32.u64 %0, t; }" : "=r"(a) : "l"(p));
    return a;
}

__device__ __forceinline__ void mma_f16(float c[4], const uint32_t a[4],
                                        uint32_t b0, uint32_t b1) {
    asm volatile(
        "mma.sync.aligned.m16n8k16.row.col.f32.f16.f16.f32 "
        "{%0,%1,%2,%3}, {%4,%5,%6,%7}, {%8,%9}, {%0,%1,%2,%3};\n"
        : "+f"(c[0]), "+f"(c[1]), "+f"(c[2]), "+f"(c[3])
        : "r"(a[0]), "r"(a[1]), "r"(a[2]), "r"(a[3]), "r"(b0), "r"(b1));
}

#define LDM_X4(r0,r1,r2,r3, addr) \
    asm volatile("ldmatrix.sync.aligned.m8n8.x4.shared.b16 {%0,%1,%2,%3}, [%4];" \
        : "=r"(r0), "=r"(r1), "=r"(r2), "=r"(r3) : "r"(addr))

#define LDM_X4_T(r0,r1,r2,r3, addr) \
    asm volatile("ldmatrix.sync.aligned.m8n8.x4.trans.shared.b16 {%0,%1,%2,%3}, [%4];" \
        : "=r"(r0), "=r"(r1), "=r"(r2), "=r"(r3) : "r"(addr))

__device__ __forceinline__ void cp16(uint32_t dst, const void* src) {
    asm volatile("cp.async.cg.shared.global [%0], [%1], 16;" :: "r"(dst), "l"(src));
}
#define CP_COMMIT() asm volatile("cp.async.commit_group;" ::: "memory")

__device__ __forceinline__ uint32_t pack_h2(float lo, float hi) {
    __half2 h = __floats2half2_rn(lo, hi);
    return *(uint32_t*)&h;
}

// ---------------------------------------------------------------------------
// fp32 -> fp16 pre-round (8 elements/thread, 16B stores)
// ---------------------------------------------------------------------------
__global__ void __launch_bounds__(256) f16_round_kernel(
    const float4* __restrict__ in, uint4* __restrict__ out)
{
    int i = blockIdx.x * 256 + threadIdx.x;
    float4 a = in[2 * i], b = in[2 * i + 1];
    uint4 o;
    o.x = pack_h2(a.x, a.y);
    o.y = pack_h2(a.z, a.w);
    o.z = pack_h2(b.x, b.y);
    o.w = pack_h2(b.z, b.w);
    out[i] = o;
}

// ---------------------------------------------------------------------------
// fp16 GEMM: C[M,N] = A[M,K] * B[N,K]^T  (fp32 accum).
// 128x128x64 tiles, 256 thr (8 warps, warp 64x32), 3-stage cp.async, ldmatrix.
// HALF_OUT: write C as half (qkv path) else float (final output).
// ---------------------------------------------------------------------------
#define GST 72                                   // smem row stride in halfs
#define GROWB (GST * 2)                          // 144 bytes
#define GMAT_BYTES (128 * GROWB)                 // 18432 per matrix
#define GSTAGE_BYTES (2 * GMAT_BYTES)            // 36864
#define GSM_BYTES (3 * GSTAGE_BYTES)             // 110592

template<bool HALF_OUT>
__global__ void __launch_bounds__(256, 2) gemm_f16_kernel(
    const __half* __restrict__ A, const __half* __restrict__ Bm,
    void* __restrict__ Cv, int N, int K)
{
    extern __shared__ char smc[];
    const uint32_t sm_base = smem_u32(smc);

    const int tid  = threadIdx.x;
    const int warp = tid >> 5, lane = tid & 31;
    const int g = lane >> 2, t = lane & 3;
    const int wm = warp & 1;        // 64-row half
    const int wn = warp >> 1;       // 32-col quarter
    const int m0 = blockIdx.y * 128, n0 = blockIdx.x * 128;
    const int NKT = K >> 6;

    // ldmatrix lane address parts (bytes)
    const uint32_t aLane = (uint32_t)(wm * 64 + (lane & 15)) * GROWB + (lane & 16);
    const uint32_t bLane = (uint32_t)(wn * 32 + (lane & 15)) * GROWB + (lane & 16);

    float acc[4][4][4];
    #pragma unroll
    for (int i = 0; i < 4; i++)
        #pragma unroll
        for (int j = 0; j < 4; j++)
            #pragma unroll
            for (int k = 0; k < 4; k++) acc[i][j][k] = 0.f;

    auto issue = [&](int kt) {
        uint32_t sA = sm_base + (uint32_t)(kt % 3) * GSTAGE_BYTES;
        uint32_t sB = sA + GMAT_BYTES;
        #pragma unroll
        for (int i = 0; i < 4; i++) {
            int idx = tid + i * 256;          // 0..1023
            int row = idx >> 3, ch = idx & 7; // 8 x 16B per 64-half row
            uint32_t so = (uint32_t)row * GROWB + ch * 16;
            cp16(sA + so, &A[(size_t)(m0 + row) * K + kt * 64 + ch * 8]);
            cp16(sB + so, &Bm[(size_t)(n0 + row) * K + kt * 64 + ch * 8]);
        }
    };

    issue(0); CP_COMMIT();
    issue(1); CP_COMMIT();
    issue(2); CP_COMMIT();

    for (int kt = 0; kt < NKT; kt++) {
        asm volatile("cp.async.wait_group 2;" ::: "memory");
        __syncthreads();
        uint32_t sA = sm_base + (uint32_t)(kt % 3) * GSTAGE_BYTES;
        uint32_t sB = sA + GMAT_BYTES;

        #pragma unroll
        for (int ks = 0; ks < 4; ks++) {
            uint32_t a[4][4];
            #pragma unroll
            for (int mt = 0; mt < 4; mt++)
                LDM_X4(a[mt][0], a[mt][1], a[mt][2], a[mt][3],
                       sA + aLane + (uint32_t)(mt * 16) * GROWB + ks * 32);
            #pragma unroll
            for (int p = 0; p < 2; p++) {
                uint32_t b0, b1, b2, b3;
                LDM_X4(b0, b1, b2, b3,
                       sB + bLane + (uint32_t)(p * 16) * GROWB + ks * 32);
                #pragma unroll
                for (int mt = 0; mt < 4; mt++) {
                    mma_f16(acc[mt][2 * p],     a[mt], b0, b2);
                    mma_f16(acc[mt][2 * p + 1], a[mt], b1, b3);
                }
            }
        }
        __syncthreads();
        if (kt + 3 < NKT) issue(kt + 3);
        CP_COMMIT();
    }

    #pragma unroll
    for (int mt = 0; mt < 4; mt++) {
        int r0 = m0 + wm * 64 + mt * 16 + g;
        #pragma unroll
        for (int nt = 0; nt < 4; nt++) {
            int c0 = n0 + wn * 32 + nt * 8 + 2 * t;
            if (HALF_OUT) {
                __half* Ch = (__half*)Cv;
                *(uint32_t*)&Ch[(size_t)r0 * N + c0]       = pack_h2(acc[mt][nt][0], acc[mt][nt][1]);
                *(uint32_t*)&Ch[(size_t)(r0 + 8) * N + c0] = pack_h2(acc[mt][nt][2], acc[mt][nt][3]);
            } else {
                float* Cf = (float*)Cv;
                *(float2*)&Cf[(size_t)r0 * N + c0]       = make_float2(acc[mt][nt][0], acc[mt][nt][1]);
                *(float2*)&Cf[(size_t)(r0 + 8) * N + c0] = make_float2(acc[mt][nt][2], acc[mt][nt][3]);
            }
        }
    }
}

// ---------------------------------------------------------------------------
// Fused squared-ReLU attention, fp16 mma + cp.async double-buffered K/V.
// Grid: (S/128, NH, B). Block 256 (8 warps x 16 q-rows).
// S-accumulator (fp32) layout == fp16 A-fragment layout -> no shuffles.
// ---------------------------------------------------------------------------
#define AST 72
#define AROWB (AST * 2)                          // 144 bytes
#define ATILE_B (128 * AROWB)                    // 18432 per tile
// layout: Q | K0 | K1 | V0 | V1
#define AQ_OFF   0
#define AK_OFF   ATILE_B
#define AV_OFF   (3 * ATILE_B)
#define ATTN_SMEM_BYTES (5 * ATILE_B)            // 92160

__global__ void __launch_bounds__(256, 2) attn_kernel(
    const __half* __restrict__ qkv, const float* __restrict__ sn_bias,
    __half* __restrict__ o_out)
{
    extern __shared__ char smc[];
    const uint32_t base = smem_u32(smc);

    const int tid  = threadIdx.x;
    const int warp = tid >> 5, lane = tid & 31;
    const int g = lane >> 2, t = lane & 3;
    const int qt = blockIdx.x, h = blockIdx.y, b = blockIdx.z;
    const float bias = sn_bias[0];

    // ldmatrix lane address parts (bytes)
    const uint32_t qLane = (uint32_t)(warp * 16 + (lane & 15)) * AROWB + (lane & 16);
    const uint32_t kLane = (uint32_t)(lane & 15) * AROWB + (lane & 16);

    auto issueKV = [&](int kt) {
        int buf = kt & 1;
        #pragma unroll
        for (int i = 0; i < 4; i++) {
            int idx = tid + i * 256;
            int row = idx >> 3, ch = idx & 7;
            size_t gp = ((size_t)(b * SS + kt * 128 + row)) * (3 * DD) + h * ADIM + ch * 8;
            uint32_t so = (uint32_t)row * AROWB + ch * 16;
            cp16(base + AK_OFF + buf * ATILE_B + so, &qkv[gp + DD]);
            cp16(base + AV_OFF + buf * ATILE_B + so, &qkv[gp + 2 * DD]);
        }
    };

    // prologue: Q + first K/V tile in group 0
    {
        #pragma unroll
        for (int i = 0; i < 4; i++) {
            int idx = tid + i * 256;
            int row = idx >> 3, ch = idx & 7;
            size_t gp = ((size_t)(b * SS + qt * 128 + row)) * (3 * DD) + h * ADIM + ch * 8;
            cp16(base + AQ_OFF + (uint32_t)row * AROWB + ch * 16, &qkv[gp]);
        }
        issueKV(0);
        CP_COMMIT();
    }

    float Oacc[8][4];
    #pragma unroll
    for (int i = 0; i < 8; i++)
        #pragma unroll
        for (int j = 0; j < 4; j++) Oacc[i][j] = 0.f;
    float rsum0 = 0.f, rsum1 = 0.f;

    for (int kt = 0; kt < 16; kt++) {
        const int buf = kt & 1;
        if (kt + 1 < 16) {
            issueKV(kt + 1);
            CP_COMMIT();
            asm volatile("cp.async.wait_group 1;" ::: "memory");
        } else {
            asm volatile("cp.async.wait_group 0;" ::: "memory");
        }
        __syncthreads();

        const uint32_t sK = base + AK_OFF + buf * ATILE_B;
        const uint32_t sV = base + AV_OFF + buf * ATILE_B;

        // ---- S = Q K^T  (warp: 16 q-rows x 128 keys), fp32 accum
        float Sacc[16][4];
        #pragma unroll
        for (int i = 0; i < 16; i++)
            #pragma unroll
            for (int j = 0; j < 4; j++) Sacc[i][j] = 0.f;

        #pragma unroll
        for (int ks = 0; ks < 4; ks++) {
            uint32_t a[4];
            LDM_X4(a[0], a[1], a[2], a[3], base + AQ_OFF + qLane + ks * 32);
            #pragma unroll
            for (int p = 0; p < 8; p++) {
                uint32_t b0, b1, b2, b3;
                LDM_X4(b0, b1, b2, b3, sK + kLane + (uint32_t)(p * 16) * AROWB + ks * 32);
                mma_f16(Sacc[2 * p],     a, b0, b2);
                mma_f16(Sacc[2 * p + 1], a, b1, b3);
            }
        }

        // ---- t = relu(S/8 + bias)^2 in place, rowsum in fp32
        #pragma unroll
        for (int nt = 0; nt < 16; nt++) {
            float v0 = fmaxf(Sacc[nt][0] * 0.125f + bias, 0.f); v0 *= v0;
            float v1 = fmaxf(Sacc[nt][1] * 0.125f + bias, 0.f); v1 *= v1;
            float v2 = fmaxf(Sacc[nt][2] * 0.125f + bias, 0.f); v2 *= v2;
            float v3 = fmaxf(Sacc[nt][3] * 0.125f + bias, 0.f); v3 *= v3;
            rsum0 += v0 + v1;
            rsum1 += v2 + v3;
            Sacc[nt][0] = v0; Sacc[nt][1] = v1; Sacc[nt][2] = v2; Sacc[nt][3] = v3;
        }

        // ---- O += t * V : A-frag is a straight f32->f16x2 pack of Sacc
        #pragma unroll
        for (int kk = 0; kk < 8; kk++) {
            uint32_t aF[4];
            aF[0] = pack_h2(Sacc[2 * kk][0],     Sacc[2 * kk][1]);
            aF[1] = pack_h2(Sacc[2 * kk][2],     Sacc[2 * kk][3]);
            aF[2] = pack_h2(Sacc[2 * kk + 1][0], Sacc[2 * kk + 1][1]);
            aF[3] = pack_h2(Sacc[2 * kk + 1][2], Sacc[2 * kk + 1][3]);
            #pragma unroll
            for (int p = 0; p < 4; p++) {
                uint32_t b0, b1, b2, b3;
                LDM_X4_T(b0, b1, b2, b3,
                         sV + (uint32_t)(kk * 16 + (lane & 15)) * AROWB + p * 32 + (lane & 16));
                mma_f16(Oacc[2 * p],     aF, b0, b1);
                mma_f16(Oacc[2 * p + 1], aF, b2, b3);
            }
        }
        __syncthreads();   // all warps done with buf before it is refilled
    }

    // ---- normalize and write O as fp16 (feeds out-proj GEMM)
    rsum0 += __shfl_xor_sync(0xffffffffu, rsum0, 1);
    rsum0 += __shfl_xor_sync(0xffffffffu, rsum0, 2);
    rsum1 += __shfl_xor_sync(0xffffffffu, rsum1, 1);
    rsum1 += __shfl_xor_sync(0xffffffffu, rsum1, 2);
    float inv0 = 1.f / (rsum0 + 1e-32f);
    float inv1 = 1.f / (rsum1 + 1e-32f);

    const int row0 = warp * 16 + g;
    size_t ob0 = ((size_t)(b * SS + qt * 128 + row0)) * DD + h * ADIM;
    size_t ob1 = ob0 + 8 * DD;
    #pragma unroll
    for (int dt = 0; dt < 8; dt++) {
        int c = dt * 8 + 2 * t;
        *(uint32_t*)&o_out[ob0 + c] = pack_h2(Oacc[dt][0] * inv0, Oacc[dt][1] * inv0);
        *(uint32_t*)&o_out[ob1 + c] = pack_h2(Oacc[dt][2] * inv1, Oacc[dt][3] * inv1);
    }
}

// ---------------------------------------------------------------------------
// Launch
// ---------------------------------------------------------------------------
extern "C" void kernel_launch(void* const* d_in, const int* in_sizes, int n_in,
                              void* d_out, int out_size)
{
    const float* iQ      = (const float*)d_in[0];
    const float* w_qkv   = (const float*)d_in[1];
    const float* w_out   = (const float*)d_in[2];
    const float* sn_bias = (const float*)d_in[3];
    float* out = (float*)d_out;
    (void)in_sizes; (void)n_in; (void)out_size;

    cudaFuncSetAttribute(attn_kernel,
                         cudaFuncAttributeMaxDynamicSharedMemorySize, ATTN_SMEM_BYTES);
    cudaFuncSetAttribute(gemm_f16_kernel<true>,
                         cudaFuncAttributeMaxDynamicSharedMemorySize, GSM_BYTES);
    cudaFuncSetAttribute(gemm_f16_kernel<false>,
                         cudaFuncAttributeMaxDynamicSharedMemorySize, GSM_BYTES);

    __half *qkvp = nullptr, *op = nullptr, *ap = nullptr, *bp = nullptr, *wp = nullptr;
    cudaGetSymbolAddress((void**)&qkvp, g_qkv);
    cudaGetSymbolAddress((void**)&op, g_o);
    cudaGetSymbolAddress((void**)&ap, g_a);
    cudaGetSymbolAddress((void**)&bp, g_b);
    cudaGetSymbolAddress((void**)&wp, g_w);

    // 0) pre-round inputs to fp16
    f16_round_kernel<<<(MTOT * DD) / 2048, 256>>>((const float4*)iQ, (uint4*)ap);
    f16_round_kernel<<<(3 * DD * DD) / 2048, 256>>>((const float4*)w_qkv, (uint4*)bp);
    f16_round_kernel<<<(DD * DD) / 2048, 256>>>((const float4*)w_out, (uint4*)wp);

    // 1) qkv = iQ @ w_qkv^T  -> half [8192, 3072]
    gemm_f16_kernel<true><<<dim3(3 * DD / 128, MTOT / 128), 256, GSM_BYTES>>>(
        ap, bp, qkvp, 3 * DD, DD);

    // 2) fused squared-ReLU attention -> half g_o [8192, 1024]
    attn_kernel<<<dim3(SS / 128, NHH, BB), 256, ATTN_SMEM_BYTES>>>(
        qkvp, sn_bias, op);

    // 3) out = o @ w_out^T  -> float d_out
    gemm_f16_kernel<false><<<dim3(DD / 128, MTOT / 128), 256, GSM_BYTES>>>(
        op, wp, out, DD, DD);
}